// round 9
// baseline (speedup 1.0000x reference)
#include <cuda_runtime.h>
#include <cuda_bf16.h>
#include <math.h>

#define BATCH 1024
#define DD 128
#define G3 384
#define TT 96
#define NSTEP 95
#define S_ODE 132
#define S_GRU 388

typedef unsigned long long u64;
typedef unsigned short u16;

__device__ __align__(256) float g_traj[(size_t)TT * BATCH * DD];
__device__ __align__(256) float g_gi[(size_t)TT * BATCH * G3];
__device__ __align__(256) float g_h1[(size_t)TT * BATCH * DD];
__device__ __align__(256) float g_h2[(size_t)BATCH * DD];
// W_ih packed bf16: [layer][hi/lo][384*128]
__device__ __align__(256) u16 g_wbf[2 * 2 * 49152];

// ---- packed f32x2 + fast transcendental helpers ----
__device__ __forceinline__ u64 pack2(float lo, float hi) {
    u64 r; asm("mov.b64 %0,{%1,%2};" : "=l"(r) : "f"(lo), "f"(hi)); return r;
}
__device__ __forceinline__ u64 dup2(float v) { return pack2(v, v); }
__device__ __forceinline__ void unpk2(u64 v, float& lo, float& hi) {
    asm("mov.b64 {%0,%1},%2;" : "=f"(lo), "=f"(hi) : "l"(v));
}
__device__ __forceinline__ u64 ffma2(u64 a, u64 b, u64 c) {
    u64 d; asm("fma.rn.f32x2 %0,%1,%2,%3;" : "=l"(d) : "l"(a), "l"(b), "l"(c)); return d;
}
__device__ __forceinline__ u64 fadd2(u64 a, u64 b) {
    u64 d; asm("add.rn.f32x2 %0,%1,%2;" : "=l"(d) : "l"(a), "l"(b)); return d;
}
__device__ __forceinline__ float fex2(float x) { float r; asm("ex2.approx.f32 %0,%1;" : "=f"(r) : "f"(x)); return r; }
__device__ __forceinline__ float frcp(float x) { float r; asm("rcp.approx.f32 %0,%1;" : "=f"(r) : "f"(x)); return r; }
__device__ __forceinline__ float ftanh(float x) { return 1.0f - 2.0f * frcp(fex2(2.8853900817779268f * x) + 1.0f); }
__device__ __forceinline__ float fsigm(float x) { return frcp(1.0f + fex2(-1.4426950408889634f * x)); }
__device__ __forceinline__ u64 tanh2(u64 v) {
    float a, b; unpk2(v, a, b); return pack2(ftanh(a), ftanh(b));
}
__device__ __forceinline__ unsigned smem_u32(const void* p) {
    unsigned a; asm("{ .reg .u64 t; cvta.to.shared.u64 t, %1; cvt.u32.u64 %0, t; }" : "=r"(a) : "l"(p));
    return a;
}

// ---- legacy warp MMA (fallback HMMA path; sm_80+ PTX, valid on sm_103) ----
__device__ __forceinline__ void ldmx4(unsigned (&r)[4], unsigned addr) {
    asm volatile("ldmatrix.sync.aligned.m8n8.x4.shared.b16 {%0,%1,%2,%3}, [%4];"
                 : "=r"(r[0]), "=r"(r[1]), "=r"(r[2]), "=r"(r[3]) : "r"(addr));
}
__device__ __forceinline__ void ldmx2(unsigned (&r)[2], unsigned addr) {
    asm volatile("ldmatrix.sync.aligned.m8n8.x2.shared.b16 {%0,%1}, [%2];"
                 : "=r"(r[0]), "=r"(r[1]) : "r"(addr));
}
__device__ __forceinline__ void mma16816(float (&d)[4], const unsigned (&a)[4],
                                         const unsigned (&b)[2]) {
    asm volatile("mma.sync.aligned.m16n8k16.row.col.f32.bf16.bf16.f32 "
                 "{%0,%1,%2,%3}, {%4,%5,%6,%7}, {%8,%9}, {%0,%1,%2,%3};"
                 : "+f"(d[0]), "+f"(d[1]), "+f"(d[2]), "+f"(d[3])
                 : "r"(a[0]), "r"(a[1]), "r"(a[2]), "r"(a[3]), "r"(b[0]), "r"(b[1]));
}

// ---------------------------------------------------------------------------
// Prep: pack W_ih (both layers) to bf16 hi/lo, plain [j][k] layout.
// ---------------------------------------------------------------------------
__global__ void __launch_bounds__(256)
prep_w(const float* __restrict__ W0, const float* __restrict__ W1)
{
    const int idx = blockIdx.x * 256 + threadIdx.x;   // 24576 total
    const int layer = idx / 12288, rem = idx - layer * 12288;
    const int j = rem >> 5, k0 = (rem & 31) * 4;
    const float4 v = *(const float4*)((layer ? W1 : W0) + (size_t)j * 128 + k0);
    const float x[4] = {v.x, v.y, v.z, v.w};
    u64 hiw = 0, low = 0;
#pragma unroll
    for (int m = 0; m < 4; m++) {
        const __nv_bfloat16 h = __float2bfloat16_rn(x[m]);
        const __nv_bfloat16 l = __float2bfloat16_rn(x[m] - __bfloat162float(h));
        hiw |= (u64)__bfloat16_as_ushort(h) << (16 * m);
        low |= (u64)__bfloat16_as_ushort(l) << (16 * m);
    }
    u16* dst = g_wbf + (size_t)layer * 98304 + (size_t)j * 128 + k0;
    *(u64*)(dst) = hiw;
    *(u64*)(dst + 49152) = low;
}

// ---------------------------------------------------------------------------
// gi via legacy mma.sync: CTA = 128 items x 96 outputs. A/B bf16 hi/lo in
// padded smem (row stride 136 bf16 = 272B, conflict-free ldmatrix).
// D = Ahi*Bhi + Ahi*Blo + Alo*Bhi (fp32 accum).
// ---------------------------------------------------------------------------
#define GA_HI 512
#define GA_LO (GA_HI + 34816)
#define GB_HI (GA_LO + 34816)
#define GB_LO (GB_HI + 26112)
#define SM_GIB (GB_LO + 26112)   // 122,368 B

__global__ void __launch_bounds__(256)
gi_mma(const float* __restrict__ X, const u16* __restrict__ whi,
       const float* __restrict__ bih, float* __restrict__ gi)
{
    extern __shared__ __align__(256) unsigned char smraw[];
    const unsigned smb = smem_u32(smraw);
    float* sbias = (float*)smraw;
    const int tid = threadIdx.x, wid = tid >> 5, lane = tid & 31;
    const int tilei = blockIdx.x >> 2, nq = blockIdx.x & 3;
    const int item0 = tilei * 128, jbase = nq * 96;
    const u16* wlo = whi + 49152;

    if (tid < 96) sbias[tid] = bih[jbase + tid];
    // B: copy 96 rows x 128 bf16 (hi & lo) into padded smem
    for (int i = tid; i < 1536; i += 256) {
        const int j = i >> 4, kq = i & 15;
        const unsigned doff = (unsigned)(j * 136 + kq * 8) * 2;
        *(uint4*)(smraw + GB_HI + doff) = *(const uint4*)(whi + (size_t)(jbase + j) * 128 + kq * 8);
        *(uint4*)(smraw + GB_LO + doff) = *(const uint4*)(wlo + (size_t)(jbase + j) * 128 + kq * 8);
    }
    // A: convert 128 items x 128 k fp32 -> bf16 hi/lo
    for (int i = tid; i < 4096; i += 256) {
        const int m = i >> 5, k0 = (i & 31) * 4;
        const float4 v = *(const float4*)(X + (size_t)(item0 + m) * DD + k0);
        const float x[4] = {v.x, v.y, v.z, v.w};
        u64 hiw = 0, low = 0;
#pragma unroll
        for (int q = 0; q < 4; q++) {
            const __nv_bfloat16 h = __float2bfloat16_rn(x[q]);
            const __nv_bfloat16 l = __float2bfloat16_rn(x[q] - __bfloat162float(h));
            hiw |= (u64)__bfloat16_as_ushort(h) << (16 * q);
            low |= (u64)__bfloat16_as_ushort(l) << (16 * q);
        }
        const unsigned doff = (unsigned)(m * 136 + k0) * 2;
        *(u64*)(smraw + GA_HI + doff) = hiw;
        *(u64*)(smraw + GA_LO + doff) = low;
    }
    __syncthreads();

    // warp wid owns M-block [wid*16, wid*16+16), all 96 N
    const int l15 = lane & 15;
    const unsigned aoff = (unsigned)(l15 * 136 + ((lane >> 4) << 3)) * 2;
    const unsigned boff = (unsigned)((l15 & 7) * 136 + ((l15 >> 3) << 3)) * 2;
    const unsigned abase = smb + GA_HI + aoff + (unsigned)wid * 16 * 272;
    const unsigned bbase = smb + GB_HI + boff;

    float d[12][4];
#pragma unroll
    for (int nb = 0; nb < 12; nb++)
#pragma unroll
        for (int m = 0; m < 4; m++) d[nb][m] = 0.0f;

#pragma unroll 1
    for (int ks = 0; ks < 8; ks++) {
        unsigned ah[4], al[4];
        ldmx4(ah, abase + ks * 32);
        ldmx4(al, abase + ks * 32 + 34816);
#pragma unroll
        for (int nb = 0; nb < 12; nb++) {
            unsigned bh[2], bl[2];
            const unsigned ba = bbase + (unsigned)nb * 2176 + ks * 32;
            ldmx2(bh, ba);
            ldmx2(bl, ba + 26112);
            mma16816(d[nb], ah, bh);
            mma16816(d[nb], ah, bl);
            mma16816(d[nb], al, bh);
        }
    }

    // epilogue: add bias, store fp32
    const int row0 = lane >> 2, col0 = (lane & 3) * 2;
    const int itemA = item0 + wid * 16 + row0;
#pragma unroll
    for (int nb = 0; nb < 12; nb++) {
        const int col = nb * 8 + col0;
        const float b0 = sbias[col], b1 = sbias[col + 1];
        float* oA = gi + (size_t)itemA * G3 + jbase + col;
        float* oB = oA + (size_t)8 * G3;
        *(float2*)(oA) = make_float2(d[nb][0] + b0, d[nb][1] + b1);
        *(float2*)(oB) = make_float2(d[nb][2] + b0, d[nb][3] + b1);
    }
}

// ---------------------------------------------------------------------------
// Phase 1: Dopri5 ODE (exact R7 version). 256 thr = 8 warps, row-pair f32x2.
// ---------------------------------------------------------------------------
__global__ void __launch_bounds__(256)
ode_kernel(const float* __restrict__ yl, const float* __restrict__ yh,
           const float* __restrict__ W, const float* __restrict__ bias)
{
    extern __shared__ float sm[];
    u64* pbuf = (u64*)(sm + S_ODE * DD);
    u64* xs   = pbuf + 4096;
    const int tid = threadIdx.x;
    for (int idx = tid; idx < DD * DD; idx += 256) {
        const int j = idx >> 7, k = idx & 127;
        sm[k * S_ODE + j] = W[idx];
    }
    const int lane = tid & 31, w = tid >> 5;
    const int q = w;
    const int p = w >> 1, jh = w & 1;
    const int j0 = 64 * jh + 2 * lane;
    const int rowA = blockIdx.x * 8 + 2 * p, rowB = rowA + 1;

    const u64 bv0 = dup2(bias[j0]), bv1 = dup2(bias[j0 + 1]);

    float a0 = (j0 < 32) ? yl[rowA * 32 + j0] : yh[rowA * 96 + j0 - 32];
    float b0 = (j0 < 32) ? yl[rowB * 32 + j0] : yh[rowB * 96 + j0 - 32];
    float a1 = (j0 + 1 < 32) ? yl[rowA * 32 + j0 + 1] : yh[rowA * 96 + j0 + 1 - 32];
    float b1 = (j0 + 1 < 32) ? yl[rowB * 32 + j0 + 1] : yh[rowB * 96 + j0 + 1 - 32];
    u64 y0 = pack2(a0, b0), y1 = pack2(a1, b1);
    *(float2*)(g_traj + (size_t)rowA * DD + j0) = make_float2(a0, a1);
    *(float2*)(g_traj + (size_t)rowB * DD + j0) = make_float2(b0, b1);
    *(ulonglong2*)(xs + p * 128 + j0) = make_ulonglong2(y0, y1);
    __syncthreads();

    const u64 dt2 = dup2(1.0f / 95.0f);
    u64 k1[2], k2[2], k3[2], k4[2], k5[2], k6[2], ar[2];

#define ODE_EVAL(KOUT) do { \
    u64 acc[4][4]; \
    _Pragma("unroll") \
    for (int pp = 0; pp < 4; pp++) { acc[pp][0]=0; acc[pp][1]=0; acc[pp][2]=0; acc[pp][3]=0; } \
    _Pragma("unroll") \
    for (int kk = 0; kk < 16; kk++) { \
        const int k = 16 * q + kk; \
        const float4 wv = *(const float4*)(sm + k * S_ODE + 4 * lane); \
        const u64 w0 = dup2(wv.x), w1 = dup2(wv.y), w2 = dup2(wv.z), w3 = dup2(wv.w); \
        const u64 x0 = xs[k], x1 = xs[128 + k], x2 = xs[256 + k], x3 = xs[384 + k]; \
        acc[0][0]=ffma2(x0,w0,acc[0][0]); acc[0][1]=ffma2(x0,w1,acc[0][1]); \
        acc[0][2]=ffma2(x0,w2,acc[0][2]); acc[0][3]=ffma2(x0,w3,acc[0][3]); \
        acc[1][0]=ffma2(x1,w0,acc[1][0]); acc[1][1]=ffma2(x1,w1,acc[1][1]); \
        acc[1][2]=ffma2(x1,w2,acc[1][2]); acc[1][3]=ffma2(x1,w3,acc[1][3]); \
        acc[2][0]=ffma2(x2,w0,acc[2][0]); acc[2][1]=ffma2(x2,w1,acc[2][1]); \
        acc[2][2]=ffma2(x2,w2,acc[2][2]); acc[2][3]=ffma2(x2,w3,acc[2][3]); \
        acc[3][0]=ffma2(x3,w0,acc[3][0]); acc[3][1]=ffma2(x3,w1,acc[3][1]); \
        acc[3][2]=ffma2(x3,w2,acc[3][2]); acc[3][3]=ffma2(x3,w3,acc[3][3]); \
    } \
    _Pragma("unroll") \
    for (int pp = 0; pp < 4; pp++) { \
        u64* base = pbuf + (size_t)(q * 4 + pp) * 128 + 4 * lane; \
        *(ulonglong2*)(base)     = make_ulonglong2(acc[pp][0], acc[pp][1]); \
        *(ulonglong2*)(base + 2) = make_ulonglong2(acc[pp][2], acc[pp][3]); \
    } \
    __syncthreads(); \
    u64 s0 = bv0, s1 = bv1; \
    _Pragma("unroll") \
    for (int qq = 0; qq < 8; qq++) { \
        const ulonglong2 v = *(const ulonglong2*)(pbuf + (size_t)(qq * 4 + p) * 128 + j0); \
        s0 = fadd2(s0, v.x); s1 = fadd2(s1, v.y); \
    } \
    KOUT[0] = tanh2(s0); KOUT[1] = tanh2(s1); \
} while (0)

#define ODE_PUSH() do { \
    *(ulonglong2*)(xs + p * 128 + j0) = make_ulonglong2(ar[0], ar[1]); \
    __syncthreads(); } while (0)

    for (int st = 0; st < NSTEP; st++) {
        ODE_EVAL(k1);
        {
            const u64 c = dup2(0.2f / 95.0f);
            ar[0] = ffma2(c, k1[0], y0); ar[1] = ffma2(c, k1[1], y1);
        }
        ODE_PUSH();

        ODE_EVAL(k2);
#pragma unroll
        for (int m = 0; m < 2; m++) {
            u64 s = ffma2(dup2(0.225f), k2[m], ffma2(dup2(0.075f), k1[m], (u64)0));
            ar[m] = ffma2(dt2, s, m ? y1 : y0);
        }
        ODE_PUSH();

        ODE_EVAL(k3);
#pragma unroll
        for (int m = 0; m < 2; m++) {
            u64 s = ffma2(dup2(0.9777777777777777f), k1[m], (u64)0);
            s = ffma2(dup2(-3.7333333333333334f), k2[m], s);
            s = ffma2(dup2(3.5555555555555554f), k3[m], s);
            ar[m] = ffma2(dt2, s, m ? y1 : y0);
        }
        ODE_PUSH();

        ODE_EVAL(k4);
#pragma unroll
        for (int m = 0; m < 2; m++) {
            u64 s = ffma2(dup2(2.9525906892141633f), k1[m], (u64)0);
            s = ffma2(dup2(-11.595793324188385f), k2[m], s);
            s = ffma2(dup2(9.822892851699436f), k3[m], s);
            s = ffma2(dup2(-0.2908093278463649f), k4[m], s);
            ar[m] = ffma2(dt2, s, m ? y1 : y0);
        }
        ODE_PUSH();

        ODE_EVAL(k5);
#pragma unroll
        for (int m = 0; m < 2; m++) {
            u64 s = ffma2(dup2(2.8462752525252526f), k1[m], (u64)0);
            s = ffma2(dup2(-10.757575757575758f), k2[m], s);
            s = ffma2(dup2(8.906422717743473f), k3[m], s);
            s = ffma2(dup2(0.2784090909090909f), k4[m], s);
            s = ffma2(dup2(-0.2735313036020583f), k5[m], s);
            ar[m] = ffma2(dt2, s, m ? y1 : y0);
        }
        ODE_PUSH();

        ODE_EVAL(k6);
#pragma unroll
        for (int m = 0; m < 2; m++) {
            u64 s = ffma2(dup2(0.09114583333333333f), k1[m], (u64)0);
            s = ffma2(dup2(0.44923629829290207f), k3[m], s);
            s = ffma2(dup2(0.6510416666666666f), k4[m], s);
            s = ffma2(dup2(-0.322376179245283f), k5[m], s);
            s = ffma2(dup2(0.13095238095238096f), k6[m], s);
            if (m == 0) y0 = ffma2(dt2, s, y0); else y1 = ffma2(dt2, s, y1);
        }
        {
            float c0, d0, c1, d1;
            unpk2(y0, c0, d0); unpk2(y1, c1, d1);
            *(float2*)(g_traj + ((size_t)(st + 1) * BATCH + rowA) * DD + j0) = make_float2(c0, c1);
            *(float2*)(g_traj + ((size_t)(st + 1) * BATCH + rowB) * DD + j0) = make_float2(d0, d1);
        }
        *(ulonglong2*)(xs + p * 128 + j0) = make_ulonglong2(y0, y1);
        __syncthreads();
    }
#undef ODE_EVAL
#undef ODE_PUSH
}

// ---------------------------------------------------------------------------
// Phase 3/5: GRU scan (exact R6 version). 384 thr, 2 barriers/t.
// ---------------------------------------------------------------------------
__global__ void __launch_bounds__(384)
gru_kernel(const float* __restrict__ gi, const float* __restrict__ Whh,
           const float* __restrict__ bhh, float* __restrict__ otraj,
           float* __restrict__ olast)
{
    extern __shared__ float sm[];
    float* pbuf = sm + DD * S_GRU;
    float* xsf  = pbuf + 6144;
    u64* xsu = (u64*)xsf;
    const int tid = threadIdx.x;
    for (int idx = tid; idx < G3 * DD; idx += 384) {
        const int j = idx >> 7, k = idx & 127;
        sm[k * S_GRU + j] = Whh[idx];
    }
    for (int idx = tid; idx < 2048; idx += 384) xsf[idx] = 0.0f;
    __syncthreads();

    const int lane = tid & 31, wid = tid >> 5;
    const int g = wid >> 2, ks = (wid >> 1) & 1, rh = wid & 1;
    const float* wb = sm + g * 128 + 4 * lane;
    float* pme = pbuf + (size_t)((g * 2 + ks) * 8 + rh * 4) * 128 + 4 * lane;
    const int frow = wid;
    const bool fin = (wid < 8);
    const int grow = blockIdx.x * 8 + frow;

    float br[4], bz[4], bn[4];
    if (fin) {
        const float4 vr = *(const float4*)(bhh + 4 * lane);
        const float4 vz = *(const float4*)(bhh + 128 + 4 * lane);
        const float4 vn = *(const float4*)(bhh + 256 + 4 * lane);
        br[0]=vr.x; br[1]=vr.y; br[2]=vr.z; br[3]=vr.w;
        bz[0]=vz.x; bz[1]=vz.y; bz[2]=vz.z; bz[3]=vz.w;
        bn[0]=vn.x; bn[1]=vn.y; bn[2]=vn.z; bn[3]=vn.w;
    }
    float h[4] = {0.f, 0.f, 0.f, 0.f};

    for (int t = 0; t < TT; t++) {
        float4 gr_, gz_, gn_;
        if (fin) {
            const float* gp = gi + ((size_t)t * BATCH + grow) * G3 + 4 * lane;
            gr_ = *(const float4*)(gp);
            gz_ = *(const float4*)(gp + 128);
            gn_ = *(const float4*)(gp + 256);
        }
        u64 acc[4][2];
#pragma unroll
        for (int r = 0; r < 4; r++) { acc[r][0] = 0; acc[r][1] = 0; }
        const int kbase = 64 * ks;
#pragma unroll 8
        for (int kk = 0; kk < 64; kk += 2) {
            const int k = kbase + kk;
            const ulonglong2 x0 = *(const ulonglong2*)(xsu + (rh * 4 + 0) * 128 + k);
            const ulonglong2 x1 = *(const ulonglong2*)(xsu + (rh * 4 + 1) * 128 + k);
            const ulonglong2 x2 = *(const ulonglong2*)(xsu + (rh * 4 + 2) * 128 + k);
            const ulonglong2 x3 = *(const ulonglong2*)(xsu + (rh * 4 + 3) * 128 + k);
            const ulonglong2 wA = *(const ulonglong2*)(wb + k * S_GRU);
            const ulonglong2 wB = *(const ulonglong2*)(wb + (k + 1) * S_GRU);
            acc[0][0] = ffma2(x0.x, wA.x, acc[0][0]); acc[0][1] = ffma2(x0.x, wA.y, acc[0][1]);
            acc[1][0] = ffma2(x1.x, wA.x, acc[1][0]); acc[1][1] = ffma2(x1.x, wA.y, acc[1][1]);
            acc[2][0] = ffma2(x2.x, wA.x, acc[2][0]); acc[2][1] = ffma2(x2.x, wA.y, acc[2][1]);
            acc[3][0] = ffma2(x3.x, wA.x, acc[3][0]); acc[3][1] = ffma2(x3.x, wA.y, acc[3][1]);
            acc[0][0] = ffma2(x0.y, wB.x, acc[0][0]); acc[0][1] = ffma2(x0.y, wB.y, acc[0][1]);
            acc[1][0] = ffma2(x1.y, wB.x, acc[1][0]); acc[1][1] = ffma2(x1.y, wB.y, acc[1][1]);
            acc[2][0] = ffma2(x2.y, wB.x, acc[2][0]); acc[2][1] = ffma2(x2.y, wB.y, acc[2][1]);
            acc[3][0] = ffma2(x3.y, wB.x, acc[3][0]); acc[3][1] = ffma2(x3.y, wB.y, acc[3][1]);
        }
#pragma unroll
        for (int r = 0; r < 4; r++)
            *(ulonglong2*)(pme + r * 128) = make_ulonglong2(acc[r][0], acc[r][1]);
        __syncthreads();

        if (fin) {
            const float* pb = pbuf + (size_t)frow * 128 + 4 * lane;
            const ulonglong2 pr0 = *(const ulonglong2*)(pb);
            const ulonglong2 pr1 = *(const ulonglong2*)(pb + 8 * 128);
            const ulonglong2 pz0 = *(const ulonglong2*)(pb + 16 * 128);
            const ulonglong2 pz1 = *(const ulonglong2*)(pb + 24 * 128);
            const ulonglong2 pn0 = *(const ulonglong2*)(pb + 32 * 128);
            const ulonglong2 pn1 = *(const ulonglong2*)(pb + 40 * 128);
            float ar[4], az[4], an[4];
            {
                const u64 s0 = fadd2(pr0.x, pr1.x), s1 = fadd2(pr0.y, pr1.y);
                unpk2(s0, ar[0], ar[1]); unpk2(s1, ar[2], ar[3]);
            }
            {
                const u64 s0 = fadd2(pz0.x, pz1.x), s1 = fadd2(pz0.y, pz1.y);
                unpk2(s0, az[0], az[1]); unpk2(s1, az[2], az[3]);
            }
            {
                const u64 s0 = fadd2(pn0.x, pn1.x), s1 = fadd2(pn0.y, pn1.y);
                unpk2(s0, an[0], an[1]); unpk2(s1, an[2], an[3]);
            }
            const float gvr[4] = {gr_.x, gr_.y, gr_.z, gr_.w};
            const float gvz[4] = {gz_.x, gz_.y, gz_.z, gz_.w};
            const float gvn[4] = {gn_.x, gn_.y, gn_.z, gn_.w};
#pragma unroll
            for (int m = 0; m < 4; m++) {
                const float rg = fsigm(gvr[m] + ar[m] + br[m]);
                const float zg = fsigm(gvz[m] + az[m] + bz[m]);
                const float ng = ftanh(gvn[m] + rg * (an[m] + bn[m]));
                h[m] = ng + zg * (h[m] - ng);
            }
            float* xme = xsf + (size_t)(frow * 128 + 4 * lane) * 2;
            *(float4*)(xme)     = make_float4(h[0], h[0], h[1], h[1]);
            *(float4*)(xme + 4) = make_float4(h[2], h[2], h[3], h[3]);
            if (otraj)
                *(float4*)(otraj + ((size_t)t * BATCH + grow) * DD + 4 * lane) =
                    make_float4(h[0], h[1], h[2], h[3]);
        }
        __syncthreads();
    }
    if (olast && fin)
        *(float4*)(olast + (size_t)grow * DD + 4 * lane) =
            make_float4(h[0], h[1], h[2], h[3]);
}

// ---------------------------------------------------------------------------
// Phase 6: FC head (unchanged).
// ---------------------------------------------------------------------------
__global__ void __launch_bounds__(256)
fc_kernel(const float* __restrict__ W1, const float* __restrict__ b1,
          const float* __restrict__ W2, const float* __restrict__ b2,
          float* __restrict__ out)
{
    extern __shared__ float sm[];
    float* hs = sm;
    float* hd = sm + 1024;
    float* wt = sm + 1536;
    const int tid = threadIdx.x;
    const int row0 = blockIdx.x * 8;

    for (int idx = tid; idx < 8 * DD; idx += 256) hs[idx] = g_h2[(size_t)row0 * DD + idx];
    for (int idx = tid; idx < 64 * DD; idx += 256) {
        const int j = idx >> 7, k = idx & 127;
        wt[k * 68 + j] = W1[idx];
    }
    __syncthreads();

#pragma unroll
    for (int i = 0; i < 2; i++) {
        const int p = tid + 256 * i, r = p >> 6, j = p & 63;
        float acc = b1[j];
#pragma unroll 8
        for (int k = 0; k < DD; k++) acc = fmaf(hs[r * DD + k], wt[k * 68 + j], acc);
        hd[r * 64 + j] = acc * normcdff(acc);
    }

    for (int c = 0; c < 12; c++) {
        __syncthreads();
        for (int idx = tid; idx < 256 * 64; idx += 256) {
            const int jj = idx >> 6, k = idx & 63;
            wt[k * 260 + jj] = W2[(size_t)(c * 256 + jj) * 64 + k];
        }
        __syncthreads();
        const int j = c * 256 + tid;
        float acc[8];
#pragma unroll
        for (int r = 0; r < 8; r++) acc[r] = b2[j];
#pragma unroll 8
        for (int k = 0; k < 64; k++) {
            const float w = wt[k * 260 + tid];
#pragma unroll
            for (int r = 0; r < 8; r++) acc[r] = fmaf(hd[r * 64 + k], w, acc[r]);
        }
#pragma unroll
        for (int r = 0; r < 8; r++) out[(size_t)(row0 + r) * 3072 + j] = acc[r];
    }
}

// ---------------------------------------------------------------------------
extern "C" void kernel_launch(void* const* d_in, const int* in_sizes, int n_in,
                              void* d_out, int out_size)
{
    (void)in_sizes; (void)n_in; (void)out_size;
    const float* yl    = (const float*)d_in[1];
    const float* yh    = (const float*)d_in[2];
    const float* W_ode = (const float*)d_in[3];
    const float* b_ode = (const float*)d_in[4];
    const float* W_ih0 = (const float*)d_in[5];
    const float* W_hh0 = (const float*)d_in[6];
    const float* b_ih0 = (const float*)d_in[7];
    const float* b_hh0 = (const float*)d_in[8];
    const float* W_ih1 = (const float*)d_in[9];
    const float* W_hh1 = (const float*)d_in[10];
    const float* b_ih1 = (const float*)d_in[11];
    const float* b_hh1 = (const float*)d_in[12];
    const float* W1    = (const float*)d_in[13];
    const float* b1    = (const float*)d_in[14];
    const float* W2    = (const float*)d_in[15];
    const float* b2    = (const float*)d_in[16];
    float* out = (float*)d_out;

    float *traj, *gibuf, *h1, *h2;
    u16* wbf;
    cudaGetSymbolAddress((void**)&traj,  g_traj);
    cudaGetSymbolAddress((void**)&gibuf, g_gi);
    cudaGetSymbolAddress((void**)&h1,    g_h1);
    cudaGetSymbolAddress((void**)&h2,    g_h2);
    cudaGetSymbolAddress((void**)&wbf,   g_wbf);

    const int SM_ODE  = S_ODE * DD * 4 + 32768 + 4096;    // 104,448 B
    const int SM_GRU2 = (S_GRU * DD + 6144 + 2048) * 4;   // 231,424 B
    const int SM_FC   = (1536 + 64 * 260) * 4;            //  72,704 B
    cudaFuncSetAttribute(ode_kernel, cudaFuncAttributeMaxDynamicSharedMemorySize, SM_ODE);
    cudaFuncSetAttribute(gi_mma,     cudaFuncAttributeMaxDynamicSharedMemorySize, SM_GIB);
    cudaFuncSetAttribute(gru_kernel, cudaFuncAttributeMaxDynamicSharedMemorySize, SM_GRU2);
    cudaFuncSetAttribute(fc_kernel,  cudaFuncAttributeMaxDynamicSharedMemorySize, SM_FC);

    prep_w    <<<96, 256>>>(W_ih0, W_ih1);
    ode_kernel<<<128, 256, SM_ODE>>>(yl, yh, W_ode, b_ode);
    gi_mma    <<<3072, 256, SM_GIB>>>(traj, wbf, b_ih0, gibuf);
    gru_kernel<<<128, 384, SM_GRU2>>>(gibuf, W_hh0, b_hh0, h1, nullptr);
    gi_mma    <<<3072, 256, SM_GIB>>>(h1, wbf + 98304, b_ih1, gibuf);
    gru_kernel<<<128, 384, SM_GRU2>>>(gibuf, W_hh1, b_hh1, nullptr, h2);
    fc_kernel <<<128, 256, SM_FC>>>(W1, b1, W2, b2, out);
}